// round 6
// baseline (speedup 1.0000x reference)
#include <cuda_runtime.h>
#include <math_constants.h>
#include <cstddef>

// HybridQuanvolutionEstimator — fully fused:
//   conv2x2/s2 -> closed-form quantum features -> linear(784->10) -> log_softmax
//
// Quantum circuit reduced analytically (see derivation):
//   f0 = cos(a0+t0)
//   f1 = f0 * cos(t1)*cos(a1)
//   f2 = f1 * cos(a2)
//   f3 = cos(t1)*cos(a1)*cos(a2)*cos(a3+t3)
// (t2 / Rz has no effect on Z expectations.)

#define NTHREADS 320

__global__ __launch_bounds__(NTHREADS, 4)
void hq_fused_kernel(const float* __restrict__ x,        // [B,1,28,28]
                     const float* __restrict__ conv_w,   // [4,1,2,2]
                     const float* __restrict__ conv_b,   // [4]
                     const float* __restrict__ q_theta,  // [4]
                     const float* __restrict__ lin_w,    // [10,784]
                     const float* __restrict__ lin_b,    // [10]
                     float* __restrict__ out)            // [B,10]
{
    __shared__ __align__(16) float xs[784];    // input image row
    __shared__ __align__(16) float flat[784];  // conv out (channel-major) -> qf in place
    __shared__ float swb[20];                  // conv_w (16) + conv_b (4)
    __shared__ float slogits[10];

    const int t = threadIdx.x;
    const int b = blockIdx.x;

    // ---- stage 0: loads ----
    const float4* xrow = reinterpret_cast<const float4*>(x + (size_t)b * 784);
    if (t < 196) reinterpret_cast<float4*>(xs)[t] = xrow[t];
    if (t < 16)       swb[t] = conv_w[t];
    else if (t < 20)  swb[t] = conv_b[t - 16];

    const float t0  = q_theta[0];
    const float ct1 = cosf(q_theta[1]);
    const float t3  = q_theta[3];
    __syncthreads();

    // ---- stage 1: conv 2x2 stride 2, channel-major flat[ch*196 + r*14 + c] ----
    #pragma unroll
    for (int m = t; m < 784; m += NTHREADS) {
        int ch = m / 196;
        int rc = m - ch * 196;
        int r  = rc / 14;
        int c  = rc - r * 14;
        const float* wr = &swb[ch * 4];
        int base = r * 56 + c * 2;              // (2r)*28 + 2c
        float v = swb[16 + ch]
                + wr[0] * xs[base]      + wr[1] * xs[base + 1]
                + wr[2] * xs[base + 28] + wr[3] * xs[base + 29];
        flat[m] = v;
    }
    __syncthreads();

    // ---- stage 2: quantum features per patch, in place (patch n = flat[4n..4n+3]) ----
    if (t < 196) {
        float4 a = reinterpret_cast<float4*>(flat)[t];
        float f0 = cosf(a.x + t0);
        float g1 = ct1 * cosf(a.y);
        float c2 = cosf(a.z);
        float f1 = f0 * g1;
        float f2 = f1 * c2;
        float f3 = g1 * c2 * cosf(a.w + t3);
        reinterpret_cast<float4*>(flat)[t] = make_float4(f0, f1, f2, f3);
    }
    __syncthreads();

    // ---- stage 3: logits, one warp per output class ----
    const int wid  = t >> 5;
    const int lane = t & 31;
    if (wid < 10) {
        const float* w = lin_w + wid * 784;
        float acc = 0.f;
        #pragma unroll 5
        for (int i = lane; i < 784; i += 32)
            acc = fmaf(flat[i], __ldg(w + i), acc);
        #pragma unroll
        for (int off = 16; off; off >>= 1)
            acc += __shfl_xor_sync(0xffffffffu, acc, off);
        if (lane == 0) slogits[wid] = acc + lin_b[wid];
    }
    __syncthreads();

    // ---- stage 4: log_softmax over 10, warp 0 ----
    if (t < 32) {
        float v = (t < 10) ? slogits[t] : -CUDART_INF_F;
        float mx = v;
        #pragma unroll
        for (int off = 16; off; off >>= 1)
            mx = fmaxf(mx, __shfl_xor_sync(0xffffffffu, mx, off));
        float e = (t < 10) ? expf(v - mx) : 0.f;
        float s = e;
        #pragma unroll
        for (int off = 16; off; off >>= 1)
            s += __shfl_xor_sync(0xffffffffu, s, off);
        if (t < 10) out[(size_t)b * 10 + t] = v - mx - logf(s);
    }
}

extern "C" void kernel_launch(void* const* d_in, const int* in_sizes, int n_in,
                              void* d_out, int out_size)
{
    const float* x       = (const float*)d_in[0];
    const float* conv_w  = (const float*)d_in[1];
    const float* conv_b  = (const float*)d_in[2];
    const float* q_theta = (const float*)d_in[3];
    const float* lin_w   = (const float*)d_in[4];
    const float* lin_b   = (const float*)d_in[5];
    float* out = (float*)d_out;

    int batch = in_sizes[0] / 784;  // 4096

    hq_fused_kernel<<<batch, NTHREADS>>>(x, conv_w, conv_b, q_theta,
                                         lin_w, lin_b, out);
}

// round 7
// speedup vs baseline: 1.2117x; 1.2117x over previous
#include <cuda_runtime.h>
#include <math_constants.h>
#include <cstddef>
#include <cstdint>

// HybridQuanvolutionEstimator — fully fused, register-resident:
//   conv2x2/s2 -> closed-form quantum features -> linear(784->10) -> log_softmax
//
// Quantum circuit reduced analytically:
//   f0 = cos(a0+t0)
//   f1 = f0 * cos(t1)*cos(a1)
//   f2 = f1 * cos(a2)
//   f3 = cos(t1)*cos(a1)*cos(a2)*cos(a3+t3)
// (Rz/t2 has no effect on Z expectations.)
//
// Key structural facts:
//  - patch n's angles are flat[4n..4n+3] (channel-major reinterpret), and
//    196 = 4*49 means a quad never straddles a conv channel: ch = t/49.
//  - thread t owns quad t: computes conv+features in regs, dots against a
//    register-cached lin_w quad for all 10 classes. No smem round-trip.

#define NT  224   // 7 warps; threads 196..223 are padding for full-warp shuffles
#define IMG 4     // images per block (amortizes the 40-reg weight cache)

__device__ __forceinline__ void cp16(void* smem_dst, const void* gsrc) {
    uint32_t d = (uint32_t)__cvta_generic_to_shared(smem_dst);
    asm volatile("cp.async.ca.shared.global [%0], [%1], 16;" :: "r"(d), "l"(gsrc));
}
__device__ __forceinline__ void cp_commit() {
    asm volatile("cp.async.commit_group;");
}
__device__ __forceinline__ void cp_wait_all() {
    asm volatile("cp.async.wait_group 0;" ::: "memory");
}

__global__ __launch_bounds__(NT, 3)
void hq_fused_kernel(const float* __restrict__ x,        // [B,1,28,28]
                     const float* __restrict__ conv_w,   // [4,1,2,2]
                     const float* __restrict__ conv_b,   // [4]
                     const float* __restrict__ q_theta,  // [4]
                     const float* __restrict__ lin_w,    // [10,784]
                     const float* __restrict__ lin_b,    // [10]
                     float* __restrict__ out,            // [B,10]
                     int batch)
{
    __shared__ __align__(16) float xs[2][784];  // double-buffered input image
    __shared__ __align__(16) float4 swb[4];     // conv weights per channel
    __shared__ float sbias[4];
    __shared__ float part[7][10];               // per-warp logit partials

    const int t    = threadIdx.x;
    const int lane = t & 31;
    const int wid  = t >> 5;
    const int b0   = blockIdx.x * IMG;
    const bool act = (t < 196);

    // ---- one-time: cache this thread's lin_w quad for all 10 classes (packed f32x2) ----
    unsigned long long w01[10], w23[10];
    if (act) {
        #pragma unroll
        for (int o = 0; o < 10; o++) {
            float4 wv = reinterpret_cast<const float4*>(lin_w)[o * 196 + t];
            asm("mov.b64 %0, {%1,%2};" : "=l"(w01[o]) : "f"(wv.x), "f"(wv.y));
            asm("mov.b64 %0, {%1,%2};" : "=l"(w23[o]) : "f"(wv.z), "f"(wv.w));
        }
    } else {
        #pragma unroll
        for (int o = 0; o < 10; o++) { w01[o] = 0ull; w23[o] = 0ull; }
    }
    if (t < 4) { swb[t] = reinterpret_cast<const float4*>(conv_w)[t]; sbias[t] = conv_b[t]; }

    const float t0  = q_theta[0];
    const float ct1 = __cosf(q_theta[1]);
    const float t3  = q_theta[3];
    const float lbv = (wid == 0 && lane < 10) ? lin_b[lane] : 0.f;

    // prefetch image 0
    if (act && b0 < batch)
        cp16(&xs[0][t * 4], x + (size_t)b0 * 784 + t * 4);
    cp_commit();

    for (int i = 0; i < IMG; i++) {
        const int b = b0 + i;
        if (b >= batch) break;

        cp_wait_all();          // image i resident
        __syncthreads();        // also guards xs[i&1] reuse and part[] reuse

        // prefetch next image while computing this one
        if (i + 1 < IMG && b + 1 < batch && act)
            cp16(&xs[(i + 1) & 1][t * 4], x + (size_t)(b + 1) * 784 + t * 4);
        cp_commit();

        const float* X = xs[i & 1];

        // ---- conv + quantum features, all in registers ----
        float f0 = 0.f, f1 = 0.f, f2 = 0.f, f3 = 0.f;
        if (act) {
            const int ch = t / 49;          // quad never straddles a channel
            const int u  = t - ch * 49;
            const float4 w = swb[ch];
            const float bb = sbias[ch];
            float a[4];
            #pragma unroll
            for (int k = 0; k < 4; k++) {
                int rc   = 4 * u + k;
                int r    = rc / 14;
                int c    = rc - r * 14;
                int base = r * 56 + 2 * c;  // (2r)*28 + 2c
                a[k] = fmaf(w.x, X[base],
                        fmaf(w.y, X[base + 1],
                         fmaf(w.z, X[base + 28],
                          fmaf(w.w, X[base + 29], bb))));
            }
            f0 = __cosf(a[0] + t0);
            float g1  = ct1 * __cosf(a[1]);
            float cc2 = __cosf(a[2]);
            f1 = f0 * g1;
            f2 = f1 * cc2;
            f3 = g1 * cc2 * __cosf(a[3] + t3);
        }

        // ---- 10-class dot, packed f32x2 FMAs ----
        unsigned long long f01, f23;
        asm("mov.b64 %0, {%1,%2};" : "=l"(f01) : "f"(f0), "f"(f1));
        asm("mov.b64 %0, {%1,%2};" : "=l"(f23) : "f"(f2), "f"(f3));
        float acc[10];
        #pragma unroll
        for (int o = 0; o < 10; o++) {
            unsigned long long r;
            asm("mul.rn.f32x2 %0, %1, %2;"     : "=l"(r) : "l"(f01), "l"(w01[o]));
            asm("fma.rn.f32x2 %0, %1, %2, %3;" : "=l"(r) : "l"(f23), "l"(w23[o]), "l"(r));
            float lo, hi;
            asm("mov.b64 {%0,%1}, %2;" : "=f"(lo), "=f"(hi) : "l"(r));
            acc[o] = lo + hi;
        }

        // ---- folded butterfly reduction: 30 shfls instead of 50 ----
        #pragma unroll
        for (int o = 0; o < 10; o++)
            acc[o] += __shfl_xor_sync(0xffffffffu, acc[o], 16);
        float c5[5];
        #pragma unroll
        for (int j = 0; j < 5; j++)
            c5[j] = (lane & 16) ? acc[j + 5] : acc[j];
        #pragma unroll
        for (int off = 8; off >= 1; off >>= 1) {
            #pragma unroll
            for (int j = 0; j < 5; j++)
                c5[j] += __shfl_xor_sync(0xffffffffu, c5[j], off);
        }
        if (lane == 0) {
            #pragma unroll
            for (int j = 0; j < 5; j++) part[wid][j] = c5[j];
        } else if (lane == 16) {
            #pragma unroll
            for (int j = 0; j < 5; j++) part[wid][5 + j] = c5[j];
        }
        __syncthreads();

        // ---- final combine + log_softmax (warp 0) ----
        if (wid == 0) {
            float v = -CUDART_INF_F;
            if (lane < 10) {
                v = lbv;
                #pragma unroll
                for (int p = 0; p < 7; p++) v += part[p][lane];
            }
            float mx = v;
            #pragma unroll
            for (int off = 16; off; off >>= 1)
                mx = fmaxf(mx, __shfl_xor_sync(0xffffffffu, mx, off));
            float e = (lane < 10) ? __expf(v - mx) : 0.f;
            float s = e;
            #pragma unroll
            for (int off = 16; off; off >>= 1)
                s += __shfl_xor_sync(0xffffffffu, s, off);
            if (lane < 10)
                out[(size_t)b * 10 + lane] = v - mx - __logf(s);
        }
    }
}

extern "C" void kernel_launch(void* const* d_in, const int* in_sizes, int n_in,
                              void* d_out, int out_size)
{
    const float* x       = (const float*)d_in[0];
    const float* conv_w  = (const float*)d_in[1];
    const float* conv_b  = (const float*)d_in[2];
    const float* q_theta = (const float*)d_in[3];
    const float* lin_w   = (const float*)d_in[4];
    const float* lin_b   = (const float*)d_in[5];
    float* out = (float*)d_out;

    int batch = in_sizes[0] / 784;            // 4096
    int grid  = (batch + IMG - 1) / IMG;      // 1024

    hq_fused_kernel<<<grid, NT>>>(x, conv_w, conv_b, q_theta, lin_w, lin_b,
                                  out, batch);
}

// round 10
// speedup vs baseline: 1.5802x; 1.3041x over previous
#include <cuda_runtime.h>
#include <math_constants.h>
#include <cstddef>
#include <cstdint>

// HybridQuanvolutionEstimator — fully fused, register-resident:
//   conv2x2/s2 -> closed-form quantum features -> linear(784->10) -> log_softmax
//
// Quantum circuit reduced analytically:
//   f0 = cos(a0+t0)
//   f1 = f0 * cos(t1)*cos(a1)
//   f2 = f1 * cos(a2)
//   f3 = cos(t1)*cos(a1)*cos(a2)*cos(a3+t3)
// (Rz/t2 has no effect on Z expectations.)
//
// Structure: thread t owns feature-quad t (flat[4t..4t+3]); 196 = 4*49 means a
// quad never straddles a conv channel (ch = t/49). Weight quads for all 10
// classes live in registers for the whole block (reused across IMG images).
// Per-image softmax is deferred: warp partials land in smem, and after the
// image loop warps 0..IMG-1 finish one image each in parallel.

#define NT  224   // 7 warps; threads 196..223 pad to full warps
#define IMG 4     // images per block

__device__ __forceinline__ void cp16(void* smem_dst, const void* gsrc) {
    uint32_t d = (uint32_t)__cvta_generic_to_shared(smem_dst);
    asm volatile("cp.async.ca.shared.global [%0], [%1], 16;" :: "r"(d), "l"(gsrc));
}
__device__ __forceinline__ void cp_commit() {
    asm volatile("cp.async.commit_group;");
}
__device__ __forceinline__ void cp_wait_all() {
    asm volatile("cp.async.wait_group 0;" ::: "memory");
}

__global__ __launch_bounds__(NT, 4)
void hq_fused_kernel(const float* __restrict__ x,        // [B,1,28,28]
                     const float* __restrict__ conv_w,   // [4,1,2,2]
                     const float* __restrict__ conv_b,   // [4]
                     const float* __restrict__ q_theta,  // [4]
                     const float* __restrict__ lin_w,    // [10,784]
                     const float* __restrict__ lin_b,    // [10]
                     float* __restrict__ out,            // [B,10]
                     int batch)
{
    __shared__ __align__(16) float xs[2][784];   // double-buffered input image
    __shared__ __align__(16) float4 swb[4];      // conv weights per channel
    __shared__ float sbias[4];
    __shared__ float part[IMG][7][10];           // per-image, per-warp partials

    const int t    = threadIdx.x;
    const int lane = t & 31;
    const int wid  = t >> 5;
    const int b0   = blockIdx.x * IMG;
    const bool act = (t < 196);

    // ---- one-time: register-cache this thread's lin_w quad for 10 classes ----
    float4 wq[10];
    #pragma unroll
    for (int o = 0; o < 10; o++)
        wq[o] = act ? reinterpret_cast<const float4*>(lin_w)[o * 196 + t]
                    : make_float4(0.f, 0.f, 0.f, 0.f);

    if (t < 4) { swb[t] = reinterpret_cast<const float4*>(conv_w)[t]; sbias[t] = conv_b[t]; }

    const float t0  = q_theta[0];
    const float ct1 = __cosf(q_theta[1]);
    const float t3  = q_theta[3];

    // prefetch image 0
    if (act && b0 < batch)
        cp16(&xs[0][t * 4], x + (size_t)b0 * 784 + t * 4);
    cp_commit();

    const int ch = act ? (t / 49) : 0;
    const int u  = act ? (t - ch * 49) : 0;

    #pragma unroll
    for (int i = 0; i < IMG; i++) {
        const int b = b0 + i;
        if (b >= batch) break;

        cp_wait_all();           // image i resident
        __syncthreads();         // guard xs[(i+1)&1] (last read 2 iters ago)

        // prefetch next image while computing this one
        if (i + 1 < IMG && b + 1 < batch && act)
            cp16(&xs[(i + 1) & 1][t * 4], x + (size_t)(b + 1) * 784 + t * 4);
        cp_commit();

        const float* X = xs[i & 1];

        // ---- conv + quantum features, in registers ----
        float f0 = 0.f, f1 = 0.f, f2 = 0.f, f3 = 0.f;
        if (act) {
            const float4 w = swb[ch];
            const float bb = sbias[ch];
            float a[4];
            #pragma unroll
            for (int k = 0; k < 4; k++) {
                int rc   = 4 * u + k;
                int r    = rc / 14;
                int c    = rc - r * 14;
                int base = r * 56 + 2 * c;      // (2r)*28 + 2c
                float2 top = *reinterpret_cast<const float2*>(X + base);
                float2 bot = *reinterpret_cast<const float2*>(X + base + 28);
                a[k] = fmaf(w.x, top.x,
                        fmaf(w.y, top.y,
                         fmaf(w.z, bot.x,
                          fmaf(w.w, bot.y, bb))));
            }
            f0 = __cosf(a[0] + t0);
            float g1  = ct1 * __cosf(a[1]);
            float cc2 = __cosf(a[2]);
            f1 = f0 * g1;
            f2 = f1 * cc2;
            f3 = g1 * cc2 * __cosf(a[3] + t3);
        }

        // ---- 10-class dot against register weight cache ----
        float acc[10];
        #pragma unroll
        for (int o = 0; o < 10; o++)
            acc[o] = fmaf(f0, wq[o].x,
                      fmaf(f1, wq[o].y,
                       fmaf(f2, wq[o].z, f3 * wq[o].w)));

        // ---- folded butterfly reduction: 30 shfls for 10 sums ----
        #pragma unroll
        for (int o = 0; o < 10; o++)
            acc[o] += __shfl_xor_sync(0xffffffffu, acc[o], 16);
        float c5[5];
        #pragma unroll
        for (int j = 0; j < 5; j++)
            c5[j] = (lane & 16) ? acc[j + 5] : acc[j];
        #pragma unroll
        for (int off = 8; off >= 1; off >>= 1) {
            #pragma unroll
            for (int j = 0; j < 5; j++)
                c5[j] += __shfl_xor_sync(0xffffffffu, c5[j], off);
        }
        if (lane == 0) {
            #pragma unroll
            for (int j = 0; j < 5; j++) part[i][wid][j] = c5[j];
        } else if (lane == 16) {
            #pragma unroll
            for (int j = 0; j < 5; j++) part[i][wid][5 + j] = c5[j];
        }
        // no second barrier: partials consumed after the loop
    }

    __syncthreads();

    // ---- deferred combine + log_softmax: warp i finishes image i ----
    if (wid < IMG) {
        const int b = b0 + wid;
        if (b < batch) {
            float v = -CUDART_INF_F;
            if (lane < 10) {
                v = lin_b[lane];
                #pragma unroll
                for (int p = 0; p < 7; p++) v += part[wid][p][lane];
            }
            float mx = v;
            #pragma unroll
            for (int off = 16; off; off >>= 1)
                mx = fmaxf(mx, __shfl_xor_sync(0xffffffffu, mx, off));
            float e = (lane < 10) ? __expf(v - mx) : 0.f;
            float s = e;
            #pragma unroll
            for (int off = 16; off; off >>= 1)
                s += __shfl_xor_sync(0xffffffffu, s, off);
            if (lane < 10)
                out[(size_t)b * 10 + lane] = v - mx - __logf(s);
        }
    }
}

extern "C" void kernel_launch(void* const* d_in, const int* in_sizes, int n_in,
                              void* d_out, int out_size)
{
    const float* x       = (const float*)d_in[0];
    const float* conv_w  = (const float*)d_in[1];
    const float* conv_b  = (const float*)d_in[2];
    const float* q_theta = (const float*)d_in[3];
    const float* lin_w   = (const float*)d_in[4];
    const float* lin_b   = (const float*)d_in[5];
    float* out = (float*)d_out;

    int batch = in_sizes[0] / 784;            // 4096
    int grid  = (batch + IMG - 1) / IMG;      // 1024

    hq_fused_kernel<<<grid, NT>>>(x, conv_w, conv_b, q_theta, lin_w, lin_b,
                                  out, batch);
}